// round 1
// baseline (speedup 1.0000x reference)
#include <cuda_runtime.h>

#define NQ 6
#define NL 3
#define ROWS_PER_THREAD 4
#define TPB 256

// Packed derived constants:
// [0..17]   c[l][q]  = cos(rx*0.5)
// [18..35]  s[l][q]  = sin(rx*0.5)
// [36..50]  st[l][k] = sigmoid(ep[l][k])
// padded to 52 (13 float4) / 64
__device__ float g_cst[64];

__global__ void qc_precompute(const float* __restrict__ rp,
                              const float* __restrict__ ep) {
    int t = threadIdx.x;
    if (t < NL * NQ) {
        int l = t / NQ, q = t % NQ;
        float rx = rp[(l * NQ + q) * 3 + 0];
        float s, c;
        sincosf(rx * 0.5f, &s, &c);
        g_cst[l * NQ + q]      = c;
        g_cst[18 + l * NQ + q] = s;
    }
    if (t < NL * (NQ - 1)) {
        int l = t / (NQ - 1), k = t % (NQ - 1);
        float e = ep[l * (NQ - 1) + k];
        g_cst[36 + l * (NQ - 1) + k] = 1.0f / (1.0f + expf(-e));
    }
    // zero padding (deterministic contents, though unused)
    if (t >= 51 && t < 64) {
        // covered by threads 51..63 when blockDim >= 64; we launch 64
        g_cst[t] = 0.0f;
    }
}

__global__ void __launch_bounds__(TPB)
qc_main(const float4* __restrict__ x4, float4* __restrict__ o4, int n_vec4) {
    int t = blockIdx.x * blockDim.x + threadIdx.x;
    int base = t * (ROWS_PER_THREAD * NQ / 4);   // 6 float4 per thread
    if (base + 5 >= n_vec4 + 6) { /* never true for exact grids; keep simple */ }
    if (base >= n_vec4) return;

    // ---- load packed constants (13x LDG.128, uniform -> L1 broadcast) ----
    float cst[52];
    const float4* g4 = reinterpret_cast<const float4*>(g_cst);
#pragma unroll
    for (int i = 0; i < 13; i++) {
        float4 v = __ldg(&g4[i]);
        cst[4 * i + 0] = v.x; cst[4 * i + 1] = v.y;
        cst[4 * i + 2] = v.z; cst[4 * i + 3] = v.w;
    }

    // ---- load 4 rows = 6 float4 (front-batched for MLP) ----
    float4 v[6];
#pragma unroll
    for (int i = 0; i < 6; i++) v[i] = x4[base + i];

    float xin[24];
#pragma unroll
    for (int i = 0; i < 6; i++) {
        xin[4 * i + 0] = v[i].x; xin[4 * i + 1] = v[i].y;
        xin[4 * i + 2] = v[i].z; xin[4 * i + 3] = v[i].w;
    }

    float outv[24];

#pragma unroll
    for (int r = 0; r < ROWS_PER_THREAD; r++) {
        float sr[NQ], si[NQ];
#pragma unroll
        for (int q = 0; q < NQ; q++) {
            float h = xin[r * NQ + q] * 1.57079632679489662f;
            __sincosf(h, &si[q], &sr[q]);   // real = cos, imag = sin
        }

#pragma unroll
        for (int l = 0; l < NL; l++) {
            // RX-style rotation (per-qubit fixed c,s)
#pragma unroll
            for (int q = 0; q < NQ; q++) {
                float c = cst[l * NQ + q];
                float s = cst[18 + l * NQ + q];
                float nr = fmaf(c, sr[q],  s * si[q]);
                float ni = fmaf(c, si[q], -s * sr[q]);
                sr[q] = nr; si[q] = ni;
            }
            // entanglement mixing on real part:
            // new[q]   = sr[q] + st[q]*0.5*(sr[q+1]-sr[q]),  q=0..4 (uses old sr[q+1])
            // new[5]   = sr[5] + st[4]*0.5*(old sr[4] - sr[5])
            float old4 = sr[4];
#pragma unroll
            for (int q = 0; q < NQ - 1; q++) {
                float sth = cst[36 + l * (NQ - 1) + q] * 0.5f;
                sr[q] = fmaf(sth, sr[q + 1] - sr[q], sr[q]);
            }
            float sth4 = cst[36 + l * (NQ - 1) + (NQ - 2)] * 0.5f;
            sr[NQ - 1] = fmaf(sth4, old4 - sr[NQ - 1], sr[NQ - 1]);
        }

        // magnitude
#pragma unroll
        for (int q = 0; q < NQ; q++) {
            float h = fmaf(sr[q], sr[q], si[q] * si[q]);
            outv[r * NQ + q] = h * rsqrtf(fmaxf(h, 1e-35f));
        }
    }

    // ---- store 6 float4 ----
#pragma unroll
    for (int i = 0; i < 6; i++) {
        float4 w;
        w.x = outv[4 * i + 0]; w.y = outv[4 * i + 1];
        w.z = outv[4 * i + 2]; w.w = outv[4 * i + 3];
        o4[base + i] = w;
    }
}

extern "C" void kernel_launch(void* const* d_in, const int* in_sizes, int n_in,
                              void* d_out, int out_size) {
    const float* x  = (const float*)d_in[0];  // (BATCH, 6) fp32
    const float* rp = (const float*)d_in[1];  // (3, 6, 3) fp32
    const float* ep = (const float*)d_in[2];  // (3, 5)    fp32
    float* out = (float*)d_out;

    qc_precompute<<<1, 64>>>(rp, ep);

    int total_f = in_sizes[0];          // BATCH * 6 = 25165824
    int n_vec4  = total_f / 4;          // 6291456 float4s
    int threads = total_f / (ROWS_PER_THREAD * NQ);   // 1048576
    int blocks  = (threads + TPB - 1) / TPB;          // 4096

    qc_main<<<blocks, TPB>>>((const float4*)x, (float4*)out, n_vec4);
}